// round 9
// baseline (speedup 1.0000x reference)
#include <cuda_runtime.h>

// Sequence_53300544143404: 2-layer LSTM (H=51), B=4096, T=1000 + 100 future.
// R7: k-split warp pairs. 26 warps = 13 h-groups x 2 k-halves. Each half-warp
// computes half the K range of its 4-h gate GEMM; the pair exchanges partial
// accumulators via smem + a named pair barrier (bar.sync hg+1, 64), then each
// half does the pointwise update for 2 of the 4 h. Doubles warps/SMSP (3.25 ->
// 6.5) at unchanged per-warp load:fma ratio to fix the R6 latency exposure.
// Weight loads warp-uniform (broadcast), value loads coalesced, folded linear
// head, 3 full barriers/step, f32x2 FMAs, cell state register-resident.

#define Hh    51
#define BATCH 4096
#define T_IN  1000
#define FUT   100
#define T_TOT (T_IN + FUT)
#define NHG   13            // h-groups of 4 h (h 0..51, h=51 zero pad)
#define NWARP (NHG * 2)     // 26 warps: (hgroup, khalf)
#define NTHR  (NWARP * 32)  // 832
#define RPC   32            // batch rows per CTA (= lanes)
#define NCTA  (BATCH / RPC) // 128

typedef unsigned long long ull;

struct SmemLayout {
    // Layer1 weights: [hg][k][16]; 16 = 4 h x 4 gates (i,f,g,o).
    // k 0..50 = W_hh1 columns, k==51 = W_ih1 (x column).
    float WA[NHG][52][16];
    // Layer2: k 0..50 = W_ih2 (h1 input), k==51 = 0 (x slot of B1),
    //         k 52..102 = W_hh2 (h2 input), k==103 = 0 (pad row of B2).
    float WB[NHG][104][16];
    // Ping-pong state buffers: B[p][k][lane]. 128B rows, coalesced.
    float B1[2][52][32];    // k 0..50 = h1, k 51 = x slot
    float B2[2][52][32];    // k 0..50 = h2, k 51 stays zero
    float BA[NHG][16];      // b_ih1 + b_hh1, [4h x 4g]
    float BB[NHG][16];      // b_ih2 + b_hh2
    // Partial-accumulator exchange: [hg][slot][j][lane].
    // slot 0: kh0's partials for h2,h3 (read by kh1)
    // slot 1: kh1's partials for h0,h1 (read by kh0)
    ull   XC[NHG][2][4][32];
    float P[NWARP][32];     // per-warp W_lin partials (2 h each)
};

__device__ __forceinline__ ull ffma2(ull a, ull b, ull c) {
    ull d;
    asm("fma.rn.f32x2 %0, %1, %2, %3;" : "=l"(d) : "l"(a), "l"(b), "l"(c));
    return d;
}
__device__ __forceinline__ ull add2(ull a, ull b) {
    ull d;
    asm("add.rn.f32x2 %0, %1, %2;" : "=l"(d) : "l"(a), "l"(b));
    return d;
}
__device__ __forceinline__ ull pack2(float lo, float hi) {
    ull r; asm("mov.b64 %0, {%1, %2};" : "=l"(r) : "f"(lo), "f"(hi)); return r;
}
__device__ __forceinline__ void unpack2(ull v, float& lo, float& hi) {
    asm("mov.b64 {%0, %1}, %2;" : "=f"(lo), "=f"(hi) : "l"(v));
}
__device__ __forceinline__ float sig_(float x) {
    return __fdividef(1.0f, 1.0f + __expf(-x));
}
__device__ __forceinline__ float tanh_(float x) {
    float a = fabsf(x);
    float e = __expf(-2.0f * a);
    float r = __fdividef(1.0f - e, 1.0f + e);
    return copysignf(r, x);
}
__device__ __forceinline__ float cell_update(ull aIF, ull aGO, float& c) {
    float gi, gf, gg, go;
    unpack2(aIF, gi, gf);
    unpack2(aGO, gg, go);
    float cn = sig_(gf) * c + sig_(gi) * tanh_(gg);
    c = cn;
    return sig_(go) * tanh_(cn);
}

// Accumulators: [h0IF,h0GO,h1IF,h1GO,h2IF,h2GO,h3IF,h3GO]
struct Acc { ull a[8]; };

// nk iterations; per k: 64B warp-uniform weights (4 LDS.128, broadcast),
// 4B/lane value (1 coalesced LDS.32), 1 pack, 8 FFMA2.
__device__ __forceinline__ void gemm_block(const float* w, const float* v, int nk, Acc& A) {
    #pragma unroll 2
    for (int k = 0; k < nk; ++k) {
        ulonglong2 w0 = *reinterpret_cast<const ulonglong2*>(w);       // h0:(i,f),(g,o)
        ulonglong2 w1 = *reinterpret_cast<const ulonglong2*>(w + 4);   // h1
        ulonglong2 w2 = *reinterpret_cast<const ulonglong2*>(w + 8);   // h2
        ulonglong2 w3 = *reinterpret_cast<const ulonglong2*>(w + 12);  // h3
        float vv = *v;
        ull pv = pack2(vv, vv);
        w += 16; v += 32;
        A.a[0] = ffma2(w0.x, pv, A.a[0]);
        A.a[1] = ffma2(w0.y, pv, A.a[1]);
        A.a[2] = ffma2(w1.x, pv, A.a[2]);
        A.a[3] = ffma2(w1.y, pv, A.a[3]);
        A.a[4] = ffma2(w2.x, pv, A.a[4]);
        A.a[5] = ffma2(w2.y, pv, A.a[5]);
        A.a[6] = ffma2(w3.x, pv, A.a[6]);
        A.a[7] = ffma2(w3.y, pv, A.a[7]);
    }
}

extern __shared__ __align__(16) char smem_raw[];

// Exchange partials within the (hg) pair and do the split pointwise update.
// kh0 updates h0,h1 (rows 4hg, 4hg+1); kh1 updates h2,h3 (rows 4hg+2, 4hg+3).
// Returns the two updated h values and stores them to the state buffer.
__device__ __forceinline__ void pair_exchange_update(
    SmemLayout* s, Acc& A, int hg, int kh, int lane,
    float* dst /* state buffer base */, float& cA, float& cB,
    float wlA, float wlB, float* pOut /* P[w] or nullptr-like unused */)
{
    if (kh == 0) {
        s->XC[hg][0][0][lane] = A.a[4];
        s->XC[hg][0][1][lane] = A.a[5];
        s->XC[hg][0][2][lane] = A.a[6];
        s->XC[hg][0][3][lane] = A.a[7];
    } else {
        s->XC[hg][1][0][lane] = A.a[0];
        s->XC[hg][1][1][lane] = A.a[1];
        s->XC[hg][1][2][lane] = A.a[2];
        s->XC[hg][1][3][lane] = A.a[3];
    }
    asm volatile("bar.sync %0, 64;" :: "r"(hg + 1) : "memory");
    float hA, hB;
    if (kh == 0) {
        ull pIF0 = add2(A.a[0], s->XC[hg][1][0][lane]);
        ull pGO0 = add2(A.a[1], s->XC[hg][1][1][lane]);
        ull pIF1 = add2(A.a[2], s->XC[hg][1][2][lane]);
        ull pGO1 = add2(A.a[3], s->XC[hg][1][3][lane]);
        hA = cell_update(pIF0, pGO0, cA);
        hB = cell_update(pIF1, pGO1, cB);
        dst[(4 * hg + 0) * 32 + lane] = hA;
        dst[(4 * hg + 1) * 32 + lane] = hB;
    } else {
        ull pIF2 = add2(A.a[4], s->XC[hg][0][0][lane]);
        ull pGO2 = add2(A.a[5], s->XC[hg][0][1][lane]);
        ull pIF3 = add2(A.a[6], s->XC[hg][0][2][lane]);
        ull pGO3 = add2(A.a[7], s->XC[hg][0][3][lane]);
        hA = cell_update(pIF2, pGO2, cA);
        hB = cell_update(pIF3, pGO3, cB);
        dst[(4 * hg + 2) * 32 + lane] = hA;
        if (4 * hg + 3 < Hh) dst[(4 * hg + 3) * 32 + lane] = hB;
    }
    if (pOut) *pOut = wlA * hA + wlB * hB;
}

__global__ __launch_bounds__(NTHR, 1)
void lstm_seq_kernel(const float* __restrict__ xin,
                     const float* __restrict__ W_ih1, const float* __restrict__ W_hh1,
                     const float* __restrict__ b_ih1, const float* __restrict__ b_hh1,
                     const float* __restrict__ W_ih2, const float* __restrict__ W_hh2,
                     const float* __restrict__ b_ih2, const float* __restrict__ b_hh2,
                     const float* __restrict__ W_lin, const float* __restrict__ b_lin,
                     float* __restrict__ out)
{
    SmemLayout* s = reinterpret_cast<SmemLayout*>(smem_raw);
    const int tid  = threadIdx.x;
    const int lane = tid & 31;
    const int wpid = tid >> 5;          // 0..25
    const int hg   = wpid >> 1;         // 0..12
    const int kh   = wpid & 1;          // k-half
    const int grow = blockIdx.x * RPC + lane;   // global batch row (< BATCH)

    // ---------------- one-time smem staging ----------------
    for (int i = tid; i < NHG * 52 * 16; i += NTHR) {
        int w = i / (52 * 16); int rem = i - w * 52 * 16; int k = rem >> 4; int j = rem & 15;
        int h = 4 * w + (j >> 2); int g = j & 3;
        float v = 0.f;
        if (h < Hh) {
            if (k < Hh)       v = W_hh1[(g * Hh + h) * Hh + k];
            else if (k == Hh) v = W_ih1[g * Hh + h];
        }
        s->WA[w][k][j] = v;
    }
    for (int i = tid; i < NHG * 104 * 16; i += NTHR) {
        int w = i / (104 * 16); int rem = i - w * 104 * 16; int k = rem >> 4; int j = rem & 15;
        int h = 4 * w + (j >> 2); int g = j & 3;
        float v = 0.f;
        if (h < Hh) {
            if (k < Hh)                      v = W_ih2[(g * Hh + h) * Hh + k];
            else if (k >= 52 && k < 52 + Hh) v = W_hh2[(g * Hh + h) * Hh + (k - 52)];
        }
        s->WB[w][k][j] = v;
    }
    for (int i = tid; i < NHG * 16; i += NTHR) {
        int w = i >> 4, j = i & 15;
        int h = 4 * w + (j >> 2); int g = j & 3;
        float a = 0.f, b = 0.f;
        if (h < Hh) {
            a = b_ih1[g * Hh + h] + b_hh1[g * Hh + h];
            b = b_ih2[g * Hh + h] + b_hh2[g * Hh + h];
        }
        s->BA[w][j] = a; s->BB[w][j] = b;
    }
    for (int i = tid; i < 2 * 52 * 32; i += NTHR) {
        s->B1[0][0][i] = 0.f;
        s->B2[0][0][i] = 0.f;
    }

    // W_lin coefficients for this warp's 2 updated h (register-resident)
    const int myh0 = 4 * hg + 2 * kh;
    const int myh1 = myh0 + 1;
    float wlA = (myh0 < Hh) ? W_lin[myh0] : 0.f;
    float wlB = (myh1 < Hh) ? W_lin[myh1] : 0.f;
    float blin = b_lin[0];

    float xv = 0.f;
    if (wpid == NWARP - 1) {
        // stage x[t=0] and prefetch x[t=1]
        s->B1[0][Hh][lane] = xin[grow * T_IN];
        xv = xin[grow * T_IN + 1];
    }
    __syncthreads();

    // k-range bases for this k-half
    const float* waBase = &s->WA[hg][kh * 26][0];        // layer1: 26 k each
    const float* wbBase = &s->WB[hg][kh * 52][0];        // layer2: 52 k each
    const int v1off = kh * 26 * 32;                      // value offset, layer1

    float cA1 = 0.f, cB1 = 0.f;   // layer1 cell states for my 2 h
    float cA2 = 0.f, cB2 = 0.f;   // layer2
    float out_prev = 0.f;

    // ---------------- time loop ----------------
    for (int t = 0; t < T_TOT; ++t) {
        const int p = t & 1;
        const float* cur1 = &s->B1[p][0][0];
        float*       nxt1 = &s->B1[p ^ 1][0][0];
        const float* cur2 = &s->B2[p][0][0];
        float*       nxt2 = &s->B2[p ^ 1][0][0];

        Acc A;
        {
            // gates1 = [W_hh1 | W_ih1] @ [h1; x] + bias1 ; my k-half only
            if (kh == 0) {
                ulonglong2 b0 = *reinterpret_cast<const ulonglong2*>(&s->BA[hg][0]);
                ulonglong2 b1 = *reinterpret_cast<const ulonglong2*>(&s->BA[hg][4]);
                ulonglong2 b2 = *reinterpret_cast<const ulonglong2*>(&s->BA[hg][8]);
                ulonglong2 b3 = *reinterpret_cast<const ulonglong2*>(&s->BA[hg][12]);
                A.a[0] = b0.x; A.a[1] = b0.y; A.a[2] = b1.x; A.a[3] = b1.y;
                A.a[4] = b2.x; A.a[5] = b2.y; A.a[6] = b3.x; A.a[7] = b3.y;
            } else {
                #pragma unroll
                for (int i = 0; i < 8; ++i) A.a[i] = 0ull;
            }
            gemm_block(waBase, cur1 + v1off + lane, 26, A);
            pair_exchange_update(s, A, hg, kh, lane, nxt1, cA1, cB1, 0.f, 0.f, nullptr);
        }
        __syncthreads();   // S2: h1_new visible

        {
            // gates2 = [W_ih2 | W_hh2] @ [h1_new; h2] + bias2
            // kh0 half reads h1_new (nxt1), kh1 half reads h2 (cur2).
            if (kh == 0) {
                ulonglong2 b0 = *reinterpret_cast<const ulonglong2*>(&s->BB[hg][0]);
                ulonglong2 b1 = *reinterpret_cast<const ulonglong2*>(&s->BB[hg][4]);
                ulonglong2 b2 = *reinterpret_cast<const ulonglong2*>(&s->BB[hg][8]);
                ulonglong2 b3 = *reinterpret_cast<const ulonglong2*>(&s->BB[hg][12]);
                A.a[0] = b0.x; A.a[1] = b0.y; A.a[2] = b1.x; A.a[3] = b1.y;
                A.a[4] = b2.x; A.a[5] = b2.y; A.a[6] = b3.x; A.a[7] = b3.y;
                gemm_block(wbBase, nxt1 + lane, 52, A);
            } else {
                #pragma unroll
                for (int i = 0; i < 8; ++i) A.a[i] = 0ull;
                gemm_block(wbBase, cur2 + lane, 52, A);
            }
            pair_exchange_update(s, A, hg, kh, lane, nxt2, cA2, cB2,
                                 wlA, wlB, &s->P[wpid][lane]);
        }
        __syncthreads();   // S3: h2_new + partials visible

        // warp 25: reduce partials -> out; stage x_{t+1}; prefetch
        if (wpid == NWARP - 1) {
            float a0 = s->P[0][lane], a1 = s->P[1][lane];
            #pragma unroll
            for (int w2 = 2; w2 < NWARP; w2 += 2) {
                a0 += s->P[w2][lane];
                a1 += s->P[w2 + 1][lane];
            }
            float o = a0 + a1 + blin;
            out_prev = o;
            out[grow * T_TOT + t] = o;
            // stage x for step t+1 into nxt1's x slot (read by GEMM-A next step)
            nxt1[Hh * 32 + lane] = (t + 1 < T_IN) ? xv : out_prev;
            if (t + 2 < T_IN) xv = xin[grow * T_IN + t + 2];
        }
        __syncthreads();   // S1 (of next step): x staged, step complete
    }
}

extern "C" void kernel_launch(void* const* d_in, const int* in_sizes, int n_in,
                              void* d_out, int out_size) {
    (void)in_sizes; (void)n_in; (void)out_size;
    const size_t smem = sizeof(SmemLayout);
    cudaFuncSetAttribute(lstm_seq_kernel, cudaFuncAttributeMaxDynamicSharedMemorySize, (int)smem);
    lstm_seq_kernel<<<NCTA, NTHR, smem>>>(
        (const float*)d_in[0],   // inputs [B, T]
        (const float*)d_in[1],   // W_ih1 [204,1]
        (const float*)d_in[2],   // W_hh1 [204,51]
        (const float*)d_in[3],   // b_ih1 [204]
        (const float*)d_in[4],   // b_hh1 [204]
        (const float*)d_in[5],   // W_ih2 [204,51]
        (const float*)d_in[6],   // W_hh2 [204,51]
        (const float*)d_in[7],   // b_ih2 [204]
        (const float*)d_in[8],   // b_hh2 [204]
        (const float*)d_in[9],   // W_lin [1,51]
        (const float*)d_in[10],  // b_lin [1]
        (float*)d_out);          // out [B, 1100]
}

// round 11
// speedup vs baseline: 2.5131x; 2.5131x over previous
#include <cuda_runtime.h>
#include <cuda_bf16.h>

// Sequence_53300544143404 R11: mma.sync (HMMA) LSTM — weights register-resident.
// tcgen05 is unavailable (toolchain targets sm_100 without 'a'); mma.sync bf16
// is the supported tensor path. A = weights as hi/lo bf16 fragments in regs
// (zero weight memory traffic); B = states in smem, conflict-free strides.
// 3-combo hi/lo ~ fp32 accuracy. Warp-local pointwise, 3 barriers/step.
// 128 CTAs x 416 threads (13 warps).

#define Hh    51
#define T_IN  1000
#define T_TOT 1100
#define NWARP 13
#define NTHR  (NWARP * 32)
#define NCTA  128
#define SD1   72    // B1 row stride (bf16): bank = 4g+q, bijective
#define SD2   120   // B2 row stride (bf16): bank = 28g+q, bijective

struct S {
    __nv_bfloat16 B1[2][2][32][SD1];   // [pingpong][hi/lo][n][k] k:0..50 h1, 51 x, rest 0
    __nv_bfloat16 B2[2][2][32][SD2];   // k:0..50 h1new, 51=0, 52..102 h2, rest 0
    float G[NWARP][16][36];            // gate tiles (warp-private)
    float PH[NWARP][32];               // per-warp W_lin partials
};
#define SMEM_TOTAL ((int)sizeof(S))

#define MMA_BF16(d0,d1,d2,d3, a0,a1,a2,a3, b0,b1) \
    asm volatile("mma.sync.aligned.m16n8k16.row.col.f32.bf16.bf16.f32 " \
        "{%0,%1,%2,%3}, {%4,%5,%6,%7}, {%8,%9}, {%0,%1,%2,%3};" \
        : "+f"(d0),"+f"(d1),"+f"(d2),"+f"(d3) \
        : "r"(a0),"r"(a1),"r"(a2),"r"(a3), "r"(b0),"r"(b1))

__device__ __forceinline__ float sig_(float x) {
    return __fdividef(1.0f, 1.0f + __expf(-x));
}
__device__ __forceinline__ float tanh_(float x) {
    float a = fabsf(x);
    float e = __expf(-2.0f * a);
    float r = __fdividef(1.0f - e, 1.0f + e);
    return copysignf(r, x);
}
__device__ __forceinline__ unsigned short us_(__nv_bfloat16 b) { return __bfloat16_as_ushort(b); }
// pack (v0,v1) into hi (bf16 of v) and lo (bf16 of residual) 32-bit fragments
__device__ __forceinline__ void mk_frag(float v0, float v1, unsigned& hi, unsigned& lo) {
    __nv_bfloat16 h0 = __float2bfloat16(v0), h1 = __float2bfloat16(v1);
    hi = (unsigned)us_(h0) | ((unsigned)us_(h1) << 16);
    __nv_bfloat16 l0 = __float2bfloat16(v0 - __bfloat162float(h0));
    __nv_bfloat16 l1 = __float2bfloat16(v1 - __bfloat162float(h1));
    lo = (unsigned)us_(l0) | ((unsigned)us_(l1) << 16);
}
// gate row R = 4h+g. layer1: k 0..50 = W_hh1, 51 = W_ih1 (x col), else 0
__device__ __forceinline__ float wf1(const float* Wih1, const float* Whh1, int R, int k) {
    int h = R >> 2, g = R & 3;
    if (h >= Hh) return 0.f;
    if (k < Hh)  return Whh1[(g * Hh + h) * Hh + k];
    if (k == Hh) return Wih1[g * Hh + h];
    return 0.f;
}
// layer2: k 0..50 = W_ih2 (h1new), 52..102 = W_hh2 (h2), else 0
__device__ __forceinline__ float wf2(const float* Wih2, const float* Whh2, int R, int k) {
    int h = R >> 2, g = R & 3;
    if (h >= Hh) return 0.f;
    if (k < Hh) return Wih2[(g * Hh + h) * Hh + k];
    if (k >= 52 && k < 52 + Hh) return Whh2[(g * Hh + h) * Hh + (k - 52)];
    return 0.f;
}
__device__ __forceinline__ float bias_(const float* bi, const float* bh, int R) {
    int h = R >> 2, g = R & 3;
    if (h >= Hh) return 0.f;
    return bi[g * Hh + h] + bh[g * Hh + h];
}

extern __shared__ __align__(16) char smem_raw[];

__global__ __launch_bounds__(NTHR, 1)
void lstm_mma_kernel(const float* __restrict__ xin,
                     const float* __restrict__ W_ih1, const float* __restrict__ W_hh1,
                     const float* __restrict__ b_ih1, const float* __restrict__ b_hh1,
                     const float* __restrict__ W_ih2, const float* __restrict__ W_hh2,
                     const float* __restrict__ b_ih2, const float* __restrict__ b_hh2,
                     const float* __restrict__ W_lin, const float* __restrict__ b_lin,
                     float* __restrict__ out)
{
    S* s = reinterpret_cast<S*>(smem_raw);
    const int tid  = threadIdx.x;
    const int lane = tid & 31;
    const int w    = tid >> 5;          // 0..12
    const int g    = lane >> 2;         // mma groupID (0..7)
    const int q2   = (lane & 3) * 2;    // mma col pair base

    // ---- zero state buffers ----
    for (int i = tid; i < (int)(sizeof(s->B1) + sizeof(s->B2)) / 4; i += NTHR)
        reinterpret_cast<unsigned*>(s->B1)[i] = 0u;

    // ---- build A fragments (weights, hi/lo) in registers — once ----
    const int R0 = 16 * w + g, R1 = R0 + 8;
    unsigned A1H[4][4], A1L[4][4], A2H[7][4], A2L[7][4];
    #pragma unroll
    for (int kc = 0; kc < 4; ++kc) {
        int kb = kc * 16 + q2;
        mk_frag(wf1(W_ih1,W_hh1,R0,kb),   wf1(W_ih1,W_hh1,R0,kb+1), A1H[kc][0], A1L[kc][0]);
        mk_frag(wf1(W_ih1,W_hh1,R1,kb),   wf1(W_ih1,W_hh1,R1,kb+1), A1H[kc][1], A1L[kc][1]);
        mk_frag(wf1(W_ih1,W_hh1,R0,kb+8), wf1(W_ih1,W_hh1,R0,kb+9), A1H[kc][2], A1L[kc][2]);
        mk_frag(wf1(W_ih1,W_hh1,R1,kb+8), wf1(W_ih1,W_hh1,R1,kb+9), A1H[kc][3], A1L[kc][3]);
    }
    #pragma unroll
    for (int kc = 0; kc < 7; ++kc) {
        int kb = kc * 16 + q2;
        mk_frag(wf2(W_ih2,W_hh2,R0,kb),   wf2(W_ih2,W_hh2,R0,kb+1), A2H[kc][0], A2L[kc][0]);
        mk_frag(wf2(W_ih2,W_hh2,R1,kb),   wf2(W_ih2,W_hh2,R1,kb+1), A2H[kc][1], A2L[kc][1]);
        mk_frag(wf2(W_ih2,W_hh2,R0,kb+8), wf2(W_ih2,W_hh2,R0,kb+9), A2H[kc][2], A2L[kc][2]);
        mk_frag(wf2(W_ih2,W_hh2,R1,kb+8), wf2(W_ih2,W_hh2,R1,kb+9), A2H[kc][3], A2L[kc][3]);
    }
    const float bA0 = bias_(b_ih1, b_hh1, R0), bA1 = bias_(b_ih1, b_hh1, R1);
    const float bB0 = bias_(b_ih2, b_hh2, R0), bB1 = bias_(b_ih2, b_hh2, R1);

    // pointwise: thread owns batch col n = lane, h = 4w..4w+3
    float wl[4];
    #pragma unroll
    for (int hp = 0; hp < 4; ++hp) {
        int h = 4 * w + hp;
        wl[hp] = (h < Hh) ? W_lin[h] : 0.f;
    }
    float c1[4] = {}, c2[4] = {};

    const int grow = blockIdx.x * 32 + lane;
    float xv = 0.f, blin = 0.f;
    if (w == NWARP - 1) {
        blin = b_lin[0];
        float x0 = xin[grow * T_IN];
        __nv_bfloat16 xh = __float2bfloat16(x0);
        s->B1[0][0][lane][Hh] = xh;
        s->B1[0][1][lane][Hh] = __float2bfloat16(x0 - __bfloat162float(xh));
        xv = xin[grow * T_IN + 1];
    }
    __syncthreads();

    for (int t = 0; t < T_TOT; ++t) {
        const int p = t & 1;

        // ======== layer 1: D[16 x 32] = A1 @ B1[p] ========
        #pragma unroll
        for (int nt = 0; nt < 4; ++nt) {
            float d0 = bA0, d1 = bA0, d2 = bA1, d3 = bA1;
            const __nv_bfloat16* bh = s->B1[p][0][nt * 8 + g];
            const __nv_bfloat16* bl = s->B1[p][1][nt * 8 + g];
            #pragma unroll
            for (int kc = 0; kc < 4; ++kc) {
                unsigned b0h = *reinterpret_cast<const unsigned*>(bh + kc * 16 + q2);
                unsigned b1h = *reinterpret_cast<const unsigned*>(bh + kc * 16 + q2 + 8);
                unsigned b0l = *reinterpret_cast<const unsigned*>(bl + kc * 16 + q2);
                unsigned b1l = *reinterpret_cast<const unsigned*>(bl + kc * 16 + q2 + 8);
                MMA_BF16(d0,d1,d2,d3, A1H[kc][0],A1H[kc][1],A1H[kc][2],A1H[kc][3], b0h,b1h);
                MMA_BF16(d0,d1,d2,d3, A1H[kc][0],A1H[kc][1],A1H[kc][2],A1H[kc][3], b0l,b1l);
                MMA_BF16(d0,d1,d2,d3, A1L[kc][0],A1L[kc][1],A1L[kc][2],A1L[kc][3], b0h,b1h);
            }
            *reinterpret_cast<float2*>(&s->G[w][g][nt * 8 + q2])     = make_float2(d0, d1);
            *reinterpret_cast<float2*>(&s->G[w][g + 8][nt * 8 + q2]) = make_float2(d2, d3);
        }
        __syncwarp();
        // pointwise1 (thread: n = lane, h = 4w+hp)
        {
            float hv[4];
            #pragma unroll
            for (int hp = 0; hp < 4; ++hp) {
                float gi = s->G[w][4*hp+0][lane], gf = s->G[w][4*hp+1][lane];
                float gg = s->G[w][4*hp+2][lane], go = s->G[w][4*hp+3][lane];
                float cn = sig_(gf) * c1[hp] + sig_(gi) * tanh_(gg);
                c1[hp] = cn;
                hv[hp] = sig_(go) * tanh_(cn);
            }
            __nv_bfloat16 h0 = __float2bfloat16(hv[0]), h1 = __float2bfloat16(hv[1]);
            __nv_bfloat16 h2 = __float2bfloat16(hv[2]), h3 = __float2bfloat16(hv[3]);
            uint2 hi = make_uint2((unsigned)us_(h0) | ((unsigned)us_(h1) << 16),
                                  (unsigned)us_(h2) | ((unsigned)us_(h3) << 16));
            unsigned lo01, lo23; 
            {
                __nv_bfloat16 l0 = __float2bfloat16(hv[0] - __bfloat162float(h0));
                __nv_bfloat16 l1 = __float2bfloat16(hv[1] - __bfloat162float(h1));
                __nv_bfloat16 l2 = __float2bfloat16(hv[2] - __bfloat162float(h2));
                __nv_bfloat16 l3 = __float2bfloat16(hv[3] - __bfloat162float(h3));
                lo01 = (unsigned)us_(l0) | ((unsigned)us_(l1) << 16);
                lo23 = (unsigned)us_(l2) | ((unsigned)us_(l3) << 16);
            }
            uint2 lo = make_uint2(lo01, lo23);
            *reinterpret_cast<uint2*>(&s->B1[p ^ 1][0][lane][4 * w]) = hi;
            *reinterpret_cast<uint2*>(&s->B1[p ^ 1][1][lane][4 * w]) = lo;
            *reinterpret_cast<uint2*>(&s->B2[p][0][lane][4 * w]) = hi;
            *reinterpret_cast<uint2*>(&s->B2[p][1][lane][4 * w]) = lo;
        }
        __syncthreads();   // A: B2[p] h1new complete before MMA2 reads

        // ======== layer 2: D = A2 @ B2[p] ========
        #pragma unroll
        for (int nt = 0; nt < 4; ++nt) {
            float d0 = bB0, d1 = bB0, d2 = bB1, d3 = bB1;
            const __nv_bfloat16* bh = s->B2[p][0][nt * 8 + g];
            const __nv_bfloat16* bl = s->B2[p][1][nt * 8 + g];
            #pragma unroll
            for (int kc = 0; kc < 7; ++kc) {
                unsigned b0h = *reinterpret_cast<const unsigned*>(bh + kc * 16 + q2);
                unsigned b1h = *reinterpret_cast<const unsigned*>(bh + kc * 16 + q2 + 8);
                unsigned b0l = *reinterpret_cast<const unsigned*>(bl + kc * 16 + q2);
                unsigned b1l = *reinterpret_cast<const unsigned*>(bl + kc * 16 + q2 + 8);
                MMA_BF16(d0,d1,d2,d3, A2H[kc][0],A2H[kc][1],A2H[kc][2],A2H[kc][3], b0h,b1h);
                MMA_BF16(d0,d1,d2,d3, A2H[kc][0],A2H[kc][1],A2H[kc][2],A2H[kc][3], b0l,b1l);
                MMA_BF16(d0,d1,d2,d3, A2L[kc][0],A2L[kc][1],A2L[kc][2],A2L[kc][3], b0h,b1h);
            }
            *reinterpret_cast<float2*>(&s->G[w][g][nt * 8 + q2])     = make_float2(d0, d1);
            *reinterpret_cast<float2*>(&s->G[w][g + 8][nt * 8 + q2]) = make_float2(d2, d3);
        }
        __syncwarp();
        // pointwise2 + head partial
        {
            float hv[4];
            #pragma unroll
            for (int hp = 0; hp < 4; ++hp) {
                float gi = s->G[w][4*hp+0][lane], gf = s->G[w][4*hp+1][lane];
                float gg = s->G[w][4*hp+2][lane], go = s->G[w][4*hp+3][lane];
                float cn = sig_(gf) * c2[hp] + sig_(gi) * tanh_(gg);
                c2[hp] = cn;
                hv[hp] = sig_(go) * tanh_(cn);
            }
            __nv_bfloat16 h0 = __float2bfloat16(hv[0]), h1 = __float2bfloat16(hv[1]);
            __nv_bfloat16 h2 = __float2bfloat16(hv[2]), h3 = __float2bfloat16(hv[3]);
            __nv_bfloat16 l0 = __float2bfloat16(hv[0] - __bfloat162float(h0));
            __nv_bfloat16 l1 = __float2bfloat16(hv[1] - __bfloat162float(h1));
            __nv_bfloat16 l2 = __float2bfloat16(hv[2] - __bfloat162float(h2));
            __nv_bfloat16 l3 = __float2bfloat16(hv[3] - __bfloat162float(h3));
            uint2 hi = make_uint2((unsigned)us_(h0) | ((unsigned)us_(h1) << 16),
                                  (unsigned)us_(h2) | ((unsigned)us_(h3) << 16));
            uint2 lo = make_uint2((unsigned)us_(l0) | ((unsigned)us_(l1) << 16),
                                  (unsigned)us_(l2) | ((unsigned)us_(l3) << 16));
            *reinterpret_cast<uint2*>(&s->B2[p ^ 1][0][lane][52 + 4 * w]) = hi;
            *reinterpret_cast<uint2*>(&s->B2[p ^ 1][1][lane][52 + 4 * w]) = lo;
            s->PH[w][lane] = wl[0]*hv[0] + wl[1]*hv[1] + wl[2]*hv[2] + wl[3]*hv[3];
        }
        __syncthreads();   // B: partials + h2new visible

        if (w == NWARP - 1) {
            float o = blin;
            #pragma unroll
            for (int ww = 0; ww < NWARP; ++ww) o += s->PH[ww][lane];
            out[grow * T_TOT + t] = o;
            float xs = (t + 1 < T_IN) ? xv : o;
            __nv_bfloat16 xh = __float2bfloat16(xs);
            s->B1[p ^ 1][0][lane][Hh] = xh;
            s->B1[p ^ 1][1][lane][Hh] = __float2bfloat16(xs - __bfloat162float(xh));
            if (t + 2 < T_IN) xv = xin[grow * T_IN + t + 2];
        }
        __syncthreads();   // C: x staged, step complete
    }
}

extern "C" void kernel_launch(void* const* d_in, const int* in_sizes, int n_in,
                              void* d_out, int out_size) {
    (void)in_sizes; (void)n_in; (void)out_size;
    cudaFuncSetAttribute(lstm_mma_kernel, cudaFuncAttributeMaxDynamicSharedMemorySize, SMEM_TOTAL);
    lstm_mma_kernel<<<NCTA, NTHR, SMEM_TOTAL>>>(
        (const float*)d_in[0],   // inputs [B, T]
        (const float*)d_in[1],   // W_ih1 [204,1]
        (const float*)d_in[2],   // W_hh1 [204,51]
        (const float*)d_in[3],   // b_ih1 [204]
        (const float*)d_in[4],   // b_hh1 [204]
        (const float*)d_in[5],   // W_ih2 [204,51]
        (const float*)d_in[6],   // W_hh2 [204,51]
        (const float*)d_in[7],   // b_ih2 [204]
        (const float*)d_in[8],   // b_hh2 [204]
        (const float*)d_in[9],   // W_lin [1,51]
        (const float*)d_in[10],  // b_lin [1]
        (float*)d_out);          // out [B, 1100]
}

// round 12
// speedup vs baseline: 2.6191x; 1.0422x over previous
#include <cuda_runtime.h>
#include <cuda_fp16.h>

// Sequence_53300544143404 R12: mma.sync fp16 LSTM, 26-warp k-split pairs.
// Weights register-resident as single fp16 A-fragments (systematic 2^-12 quant,
// empirically O(1)-amplified); states fp16 hi+lo in smem (2 combos: A*Bh + A*Bl
// — exact state path). Warp pair (hg, kh) splits K of the same 16 gate rows,
// exchanges f32 partial gates via smem + named pair barrier, splits pointwise
// 2h/2h. 3 CTA barriers + 2 pair barriers per step. 128 CTAs x 832 threads.

#define Hh    51
#define T_IN  1000
#define T_TOT 1100
#define NPAIR 13
#define NWARP 26
#define NTHR  832
#define NCTA  128
#define SD1   72    // B1 row stride (fp16): bank (4g+q) bijective
#define SD2   120   // B2 row stride (fp16): bank (28g+q) bijective

struct S {
    __half B1[2][2][32][SD1];      // [pp][hi/lo][n][k] k:0..50 h1, 51 x, rest 0
    __half B2[2][2][32][SD2];      // k:0..50 h1new, 51 zero, 52..102 h2, rest 0
    float  XG[NPAIR][2][16][36];   // partial gate tiles per (pair, khalf)
    float  PH[NWARP][32];          // W_lin partials
};
#define SMEM_TOTAL ((int)sizeof(S))

#define MMA_F16(d0,d1,d2,d3, a0,a1,a2,a3, b0,b1) \
    asm volatile("mma.sync.aligned.m16n8k16.row.col.f32.f16.f16.f32 " \
        "{%0,%1,%2,%3}, {%4,%5,%6,%7}, {%8,%9}, {%0,%1,%2,%3};" \
        : "+f"(d0),"+f"(d1),"+f"(d2),"+f"(d3) \
        : "r"(a0),"r"(a1),"r"(a2),"r"(a3), "r"(b0),"r"(b1))

__device__ __forceinline__ float sig_(float x) {
    return __fdividef(1.0f, 1.0f + __expf(-x));
}
__device__ __forceinline__ float tanh_(float x) {
    float a = fabsf(x);
    float e = __expf(-2.0f * a);
    float r = __fdividef(1.0f - e, 1.0f + e);
    return copysignf(r, x);
}
__device__ __forceinline__ unsigned mkh2(float v0, float v1) {
    __half h0 = __float2half(v0), h1 = __float2half(v1);
    return (unsigned)__half_as_ushort(h0) | ((unsigned)__half_as_ushort(h1) << 16);
}
// gate row R = 4h+g. layer1: k 0..50 = W_hh1, 51 = W_ih1 (x), else 0
__device__ __forceinline__ float wf1(const float* Wih1, const float* Whh1, int R, int k) {
    int h = R >> 2, g = R & 3;
    if (h >= Hh) return 0.f;
    if (k < Hh)  return Whh1[(g * Hh + h) * Hh + k];
    if (k == Hh) return Wih1[g * Hh + h];
    return 0.f;
}
// layer2: k 0..50 = W_ih2 (h1new), 52..102 = W_hh2 (h2), else 0
__device__ __forceinline__ float wf2(const float* Wih2, const float* Whh2, int R, int k) {
    int h = R >> 2, g = R & 3;
    if (h >= Hh) return 0.f;
    if (k < Hh) return Wih2[(g * Hh + h) * Hh + k];
    if (k >= 52 && k < 52 + Hh) return Whh2[(g * Hh + h) * Hh + (k - 52)];
    return 0.f;
}
__device__ __forceinline__ float bias_(const float* bi, const float* bh, int R) {
    int h = R >> 2, g = R & 3;
    if (h >= Hh) return 0.f;
    return bi[g * Hh + h] + bh[g * Hh + h];
}

extern __shared__ __align__(16) char smem_raw[];

__global__ __launch_bounds__(NTHR, 1)
void lstm_mma_kernel(const float* __restrict__ xin,
                     const float* __restrict__ W_ih1, const float* __restrict__ W_hh1,
                     const float* __restrict__ b_ih1, const float* __restrict__ b_hh1,
                     const float* __restrict__ W_ih2, const float* __restrict__ W_hh2,
                     const float* __restrict__ b_ih2, const float* __restrict__ b_hh2,
                     const float* __restrict__ W_lin, const float* __restrict__ b_lin,
                     float* __restrict__ out)
{
    S* s = reinterpret_cast<S*>(smem_raw);
    const int tid  = threadIdx.x;
    const int lane = tid & 31;
    const int w    = tid >> 5;          // 0..25
    const int hg   = w >> 1;            // pair id 0..12
    const int kh   = w & 1;             // k-half
    const int g    = lane >> 2;         // mma groupID
    const int q2   = (lane & 3) * 2;

    // ---- zero state buffers ----
    for (int i = tid; i < (int)(sizeof(s->B1) + sizeof(s->B2)) / 4; i += NTHR)
        reinterpret_cast<unsigned*>(s->B1)[i] = 0u;

    // ---- A fragments (fp16, single) ----
    const int R0 = 16 * hg + g, R1 = R0 + 8;
    unsigned A1[2][4], A2[4][4];
    #pragma unroll
    for (int kc = 0; kc < 2; ++kc) {
        int kb = (2 * kh + kc) * 16 + q2;
        A1[kc][0] = mkh2(wf1(W_ih1,W_hh1,R0,kb),   wf1(W_ih1,W_hh1,R0,kb+1));
        A1[kc][1] = mkh2(wf1(W_ih1,W_hh1,R1,kb),   wf1(W_ih1,W_hh1,R1,kb+1));
        A1[kc][2] = mkh2(wf1(W_ih1,W_hh1,R0,kb+8), wf1(W_ih1,W_hh1,R0,kb+9));
        A1[kc][3] = mkh2(wf1(W_ih1,W_hh1,R1,kb+8), wf1(W_ih1,W_hh1,R1,kb+9));
    }
    const int k2b = kh ? 4 : 0;         // layer2 chunk base (kh0: 4 chunks, kh1: 3)
    #pragma unroll
    for (int kc = 0; kc < 4; ++kc) {    // kh1's A2[3] is all-zero (k>=112), unused
        int kb = (k2b + kc) * 16 + q2;
        A2[kc][0] = mkh2(wf2(W_ih2,W_hh2,R0,kb),   wf2(W_ih2,W_hh2,R0,kb+1));
        A2[kc][1] = mkh2(wf2(W_ih2,W_hh2,R1,kb),   wf2(W_ih2,W_hh2,R1,kb+1));
        A2[kc][2] = mkh2(wf2(W_ih2,W_hh2,R0,kb+8), wf2(W_ih2,W_hh2,R0,kb+9));
        A2[kc][3] = mkh2(wf2(W_ih2,W_hh2,R1,kb+8), wf2(W_ih2,W_hh2,R1,kb+9));
    }
    const float bA0 = kh ? 0.f : bias_(b_ih1, b_hh1, R0);
    const float bA1 = kh ? 0.f : bias_(b_ih1, b_hh1, R1);
    const float bB0 = kh ? 0.f : bias_(b_ih2, b_hh2, R0);
    const float bB1 = kh ? 0.f : bias_(b_ih2, b_hh2, R1);

    // pointwise role: this warp updates h = 4hg+2kh, +1 for all 32 columns
    const int cb = 4 * hg + 2 * kh;
    float wl0 = (cb     < Hh) ? W_lin[cb]     : 0.f;
    float wl1 = (cb + 1 < Hh) ? W_lin[cb + 1] : 0.f;
    float c1[2] = {}, c2[2] = {};

    const int grow = blockIdx.x * 32 + lane;
    float xv = 0.f, blin = 0.f;
    if (w == NWARP - 1) {
        blin = b_lin[0];
        float x0 = xin[grow * T_IN];
        __half xh = __float2half(x0);
        s->B1[0][0][lane][Hh] = xh;
        s->B1[0][1][lane][Hh] = __float2half(x0 - __half2float(xh));
        xv = xin[grow * T_IN + 1];
    }
    __syncthreads();

    for (int t = 0; t < T_TOT; ++t) {
        const int p = t & 1;

        // ======== layer 1 MMAs (my 2 k-chunks) ========
        #pragma unroll
        for (int nt = 0; nt < 4; ++nt) {
            float d0 = bA0, d1 = bA0, d2 = bA1, d3 = bA1;
            #pragma unroll
            for (int kc = 0; kc < 2; ++kc) {
                int kG = (2 * kh + kc) * 16 + q2;
                const __half* bh = &s->B1[p][0][nt * 8 + g][kG];
                const __half* bl = &s->B1[p][1][nt * 8 + g][kG];
                unsigned b0h = *reinterpret_cast<const unsigned*>(bh);
                unsigned b1h = *reinterpret_cast<const unsigned*>(bh + 8);
                unsigned b0l = *reinterpret_cast<const unsigned*>(bl);
                unsigned b1l = *reinterpret_cast<const unsigned*>(bl + 8);
                MMA_F16(d0,d1,d2,d3, A1[kc][0],A1[kc][1],A1[kc][2],A1[kc][3], b0h,b1h);
                MMA_F16(d0,d1,d2,d3, A1[kc][0],A1[kc][1],A1[kc][2],A1[kc][3], b0l,b1l);
            }
            *reinterpret_cast<float2*>(&s->XG[hg][kh][g][nt * 8 + q2])     = make_float2(d0, d1);
            *reinterpret_cast<float2*>(&s->XG[hg][kh][g + 8][nt * 8 + q2]) = make_float2(d2, d3);
        }
        asm volatile("bar.sync %0, 64;" :: "r"(hg + 1) : "memory");
        // pointwise1: my 2 h, all 32 columns (n = lane)
        {
            float hv[2];
            #pragma unroll
            for (int j = 0; j < 2; ++j) {
                int r = 4 * (2 * kh + j);
                float gi = s->XG[hg][0][r+0][lane] + s->XG[hg][1][r+0][lane];
                float gf = s->XG[hg][0][r+1][lane] + s->XG[hg][1][r+1][lane];
                float gg = s->XG[hg][0][r+2][lane] + s->XG[hg][1][r+2][lane];
                float go = s->XG[hg][0][r+3][lane] + s->XG[hg][1][r+3][lane];
                float cn = sig_(gf) * c1[j] + sig_(gi) * tanh_(gg);
                c1[j] = cn;
                hv[j] = sig_(go) * tanh_(cn);
            }
            __half h0 = __float2half(hv[0]), h1 = __float2half(hv[1]);
            unsigned hi = (unsigned)__half_as_ushort(h0) | ((unsigned)__half_as_ushort(h1) << 16);
            unsigned lo = mkh2(hv[0] - __half2float(h0), hv[1] - __half2float(h1));
            // (pair hg=12,kh=1 writes col 51 = 0 here; x-stage overwrites it below)
            *reinterpret_cast<unsigned*>(&s->B1[p ^ 1][0][lane][cb]) = hi;
            *reinterpret_cast<unsigned*>(&s->B1[p ^ 1][1][lane][cb]) = lo;
            *reinterpret_cast<unsigned*>(&s->B2[p][0][lane][cb]) = hi;
            *reinterpret_cast<unsigned*>(&s->B2[p][1][lane][cb]) = lo;
        }
        __syncthreads();   // all h1new in B2[p] before layer-2 MMAs

        // ======== layer 2 MMAs (kh0: chunks 0..3, kh1: 4..6) ========
        if (kh == 0) {
            #pragma unroll
            for (int nt = 0; nt < 4; ++nt) {
                float d0 = bB0, d1 = bB0, d2 = bB1, d3 = bB1;
                #pragma unroll
                for (int kc = 0; kc < 4; ++kc) {
                    int kG = kc * 16 + q2;
                    const __half* bh = &s->B2[p][0][nt * 8 + g][kG];
                    const __half* bl = &s->B2[p][1][nt * 8 + g][kG];
                    unsigned b0h = *reinterpret_cast<const unsigned*>(bh);
                    unsigned b1h = *reinterpret_cast<const unsigned*>(bh + 8);
                    unsigned b0l = *reinterpret_cast<const unsigned*>(bl);
                    unsigned b1l = *reinterpret_cast<const unsigned*>(bl + 8);
                    MMA_F16(d0,d1,d2,d3, A2[kc][0],A2[kc][1],A2[kc][2],A2[kc][3], b0h,b1h);
                    MMA_F16(d0,d1,d2,d3, A2[kc][0],A2[kc][1],A2[kc][2],A2[kc][3], b0l,b1l);
                }
                *reinterpret_cast<float2*>(&s->XG[hg][0][g][nt * 8 + q2])     = make_float2(d0, d1);
                *reinterpret_cast<float2*>(&s->XG[hg][0][g + 8][nt * 8 + q2]) = make_float2(d2, d3);
            }
        } else {
            #pragma unroll
            for (int nt = 0; nt < 4; ++nt) {
                float d0 = 0.f, d1 = 0.f, d2 = 0.f, d3 = 0.f;
                #pragma unroll
                for (int kc = 0; kc < 3; ++kc) {
                    int kG = (4 + kc) * 16 + q2;
                    const __half* bh = &s->B2[p][0][nt * 8 + g][kG];
                    const __half* bl = &s->B2[p][1][nt * 8 + g][kG];
                    unsigned b0h = *reinterpret_cast<const unsigned*>(bh);
                    unsigned b1h = *reinterpret_cast<const unsigned*>(bh + 8);
                    unsigned b0l = *reinterpret_cast<const unsigned*>(bl);
                    unsigned b1l = *reinterpret_cast<const unsigned*>(bl + 8);
                    MMA_F16(d0,d1,d2,d3, A2[kc][0],A2[kc][1],A2[kc][2],A2[kc][3], b0h,b1h);
                    MMA_F16(d0,d1,d2,d3, A2[kc][0],A2[kc][1],A2[kc][2],A2[kc][3], b0l,b1l);
                }
                *reinterpret_cast<float2*>(&s->XG[hg][1][g][nt * 8 + q2])     = make_float2(d0, d1);
                *reinterpret_cast<float2*>(&s->XG[hg][1][g + 8][nt * 8 + q2]) = make_float2(d2, d3);
            }
        }
        asm volatile("bar.sync %0, 64;" :: "r"(hg + 1) : "memory");
        // pointwise2 + head partial
        {
            float hv[2];
            #pragma unroll
            for (int j = 0; j < 2; ++j) {
                int r = 4 * (2 * kh + j);
                float gi = s->XG[hg][0][r+0][lane] + s->XG[hg][1][r+0][lane];
                float gf = s->XG[hg][0][r+1][lane] + s->XG[hg][1][r+1][lane];
                float gg = s->XG[hg][0][r+2][lane] + s->XG[hg][1][r+2][lane];
                float go = s->XG[hg][0][r+3][lane] + s->XG[hg][1][r+3][lane];
                float cn = sig_(gf) * c2[j] + sig_(gi) * tanh_(gg);
                c2[j] = cn;
                hv[j] = sig_(go) * tanh_(cn);
            }
            __half h0 = __float2half(hv[0]), h1 = __float2half(hv[1]);
            unsigned hi = (unsigned)__half_as_ushort(h0) | ((unsigned)__half_as_ushort(h1) << 16);
            unsigned lo = mkh2(hv[0] - __half2float(h0), hv[1] - __half2float(h1));
            *reinterpret_cast<unsigned*>(&s->B2[p ^ 1][0][lane][52 + cb]) = hi;
            *reinterpret_cast<unsigned*>(&s->B2[p ^ 1][1][lane][52 + cb]) = lo;
            s->PH[w][lane] = wl0 * hv[0] + wl1 * hv[1];
        }
        __syncthreads();   // partials + h2new visible

        if (w == NWARP - 1) {
            float o = blin;
            #pragma unroll
            for (int ww = 0; ww < NWARP; ++ww) o += s->PH[ww][lane];
            out[grow * T_TOT + t] = o;
            float xs = (t + 1 < T_IN) ? xv : o;
            __half xh = __float2half(xs);
            s->B1[p ^ 1][0][lane][Hh] = xh;
            s->B1[p ^ 1][1][lane][Hh] = __float2half(xs - __half2float(xh));
            if (t + 2 < T_IN) xv = xin[grow * T_IN + t + 2];
        }
        __syncthreads();   // x staged; step complete
    }
}

extern "C" void kernel_launch(void* const* d_in, const int* in_sizes, int n_in,
                              void* d_out, int out_size) {
    (void)in_sizes; (void)n_in; (void)out_size;
    cudaFuncSetAttribute(lstm_mma_kernel, cudaFuncAttributeMaxDynamicSharedMemorySize, SMEM_TOTAL);
    lstm_mma_kernel<<<NCTA, NTHR, SMEM_TOTAL>>>(
        (const float*)d_in[0],   // inputs [B, T]
        (const float*)d_in[1],   // W_ih1 [204,1]
        (const float*)d_in[2],   // W_hh1 [204,51]
        (const float*)d_in[3],   // b_ih1 [204]
        (const float*)d_in[4],   // b_hh1 [204]
        (const float*)d_in[5],   // W_ih2 [204,51]
        (const float*)d_in[6],   // W_hh2 [204,51]
        (const float*)d_in[7],   // b_ih2 [204]
        (const float*)d_in[8],   // b_hh2 [204]
        (const float*)d_in[9],   // W_lin [1,51]
        (const float*)d_in[10],  // b_lin [1]
        (float*)d_out);          // out [B, 1100]
}

// round 13
// speedup vs baseline: 3.2535x; 1.2422x over previous
#include <cuda_runtime.h>
#include <cuda_fp16.h>

// Sequence_53300544143404 R13: layer-pipelined mma.sync fp16 LSTM.
// Teacher phase (t<999): phase A = MMA2(t)+MMA1(t+1), phase B = pw2(t)+pw1(t+1),
// 1 pair-bar + 1 CTA-bar per step; head lagged one step (PH double-buffered).
// Future phase (101 steps): sequential with synchronous head for x-feedback.
// Weights register-resident fp16 A-fragments; states fp16 hi+lo in smem
// (2 combos); tanh.approx activations (pred. rel_err 3-5e-4 < 1e-3).
// 128 CTAs x 832 threads (26 warps = 13 pairs x 2 k-halves).

#define Hh    51
#define T_IN  1000
#define T_TOT 1100
#define NPAIR 13
#define NWARP 26
#define NTHR  832
#define NCTA  128
#define SD1   72
#define SD2   120

struct S {
    __half B1[2][2][32][SD1];        // [pp][hi/lo][n][k] k:0..50 h1, 51 x
    __half B2[2][2][32][SD2];        // k:0..50 h1new, 52..102 h2
    float  XG[NPAIR][2][2][16][36];  // [pair][layer][khalf][gaterow][n]
    float  PH[2][NWARP][32];         // double-buffered W_lin partials
};
#define SMEM_TOTAL ((int)sizeof(S))

#define MMA_F16(d0,d1,d2,d3, a0,a1,a2,a3, b0,b1) \
    asm volatile("mma.sync.aligned.m16n8k16.row.col.f32.f16.f16.f32 " \
        "{%0,%1,%2,%3}, {%4,%5,%6,%7}, {%8,%9}, {%0,%1,%2,%3};" \
        : "+f"(d0),"+f"(d1),"+f"(d2),"+f"(d3) \
        : "r"(a0),"r"(a1),"r"(a2),"r"(a3), "r"(b0),"r"(b1))
#define PAIRBAR() asm volatile("bar.sync %0, 64;" :: "r"(hg + 1) : "memory")

__device__ __forceinline__ float tanhA(float x) {
    float r; asm("tanh.approx.f32 %0, %1;" : "=f"(r) : "f"(x)); return r;
}
__device__ __forceinline__ float sigA(float x) {
    return fmaf(tanhA(0.5f * x), 0.5f, 0.5f);
}
__device__ __forceinline__ unsigned mkh2(float v0, float v1) {
    __half h0 = __float2half(v0), h1 = __float2half(v1);
    return (unsigned)__half_as_ushort(h0) | ((unsigned)__half_as_ushort(h1) << 16);
}
__device__ __forceinline__ float wf1(const float* Wih1, const float* Whh1, int R, int k) {
    int h = R >> 2, g = R & 3;
    if (h >= Hh) return 0.f;
    if (k < Hh)  return Whh1[(g * Hh + h) * Hh + k];
    if (k == Hh) return Wih1[g * Hh + h];
    return 0.f;
}
__device__ __forceinline__ float wf2(const float* Wih2, const float* Whh2, int R, int k) {
    int h = R >> 2, g = R & 3;
    if (h >= Hh) return 0.f;
    if (k < Hh) return Wih2[(g * Hh + h) * Hh + k];
    if (k >= 52 && k < 52 + Hh) return Whh2[(g * Hh + h) * Hh + (k - 52)];
    return 0.f;
}
__device__ __forceinline__ float bias_(const float* bi, const float* bh, int R) {
    int h = R >> 2, g = R & 3;
    if (h >= Hh) return 0.f;
    return bi[g * Hh + h] + bh[g * Hh + h];
}

extern __shared__ __align__(16) char smem_raw[];

__global__ __launch_bounds__(NTHR, 1)
void lstm_mma_kernel(const float* __restrict__ xin,
                     const float* __restrict__ W_ih1, const float* __restrict__ W_hh1,
                     const float* __restrict__ b_ih1, const float* __restrict__ b_hh1,
                     const float* __restrict__ W_ih2, const float* __restrict__ W_hh2,
                     const float* __restrict__ b_ih2, const float* __restrict__ b_hh2,
                     const float* __restrict__ W_lin, const float* __restrict__ b_lin,
                     float* __restrict__ out)
{
    S* s = reinterpret_cast<S*>(smem_raw);
    const int tid  = threadIdx.x;
    const int lane = tid & 31;
    const int w    = tid >> 5;
    const int hg   = w >> 1;
    const int kh   = w & 1;
    const int g    = lane >> 2;
    const int q2   = (lane & 3) * 2;

    for (int i = tid; i < (int)(sizeof(s->B1) + sizeof(s->B2)) / 4; i += NTHR)
        reinterpret_cast<unsigned*>(s->B1)[i] = 0u;

    // A fragments (fp16)
    const int R0 = 16 * hg + g, R1 = R0 + 8;
    unsigned A1[2][4], A2[4][4];
    #pragma unroll
    for (int kc = 0; kc < 2; ++kc) {
        int kb = (2 * kh + kc) * 16 + q2;
        A1[kc][0] = mkh2(wf1(W_ih1,W_hh1,R0,kb),   wf1(W_ih1,W_hh1,R0,kb+1));
        A1[kc][1] = mkh2(wf1(W_ih1,W_hh1,R1,kb),   wf1(W_ih1,W_hh1,R1,kb+1));
        A1[kc][2] = mkh2(wf1(W_ih1,W_hh1,R0,kb+8), wf1(W_ih1,W_hh1,R0,kb+9));
        A1[kc][3] = mkh2(wf1(W_ih1,W_hh1,R1,kb+8), wf1(W_ih1,W_hh1,R1,kb+9));
    }
    const int k2b = kh ? 4 : 0;
    #pragma unroll
    for (int kc = 0; kc < 4; ++kc) {
        int kb = (k2b + kc) * 16 + q2;
        A2[kc][0] = mkh2(wf2(W_ih2,W_hh2,R0,kb),   wf2(W_ih2,W_hh2,R0,kb+1));
        A2[kc][1] = mkh2(wf2(W_ih2,W_hh2,R1,kb),   wf2(W_ih2,W_hh2,R1,kb+1));
        A2[kc][2] = mkh2(wf2(W_ih2,W_hh2,R0,kb+8), wf2(W_ih2,W_hh2,R0,kb+9));
        A2[kc][3] = mkh2(wf2(W_ih2,W_hh2,R1,kb+8), wf2(W_ih2,W_hh2,R1,kb+9));
    }
    const float bA0 = kh ? 0.f : bias_(b_ih1, b_hh1, R0);
    const float bA1 = kh ? 0.f : bias_(b_ih1, b_hh1, R1);
    const float bB0 = kh ? 0.f : bias_(b_ih2, b_hh2, R0);
    const float bB1 = kh ? 0.f : bias_(b_ih2, b_hh2, R1);

    const int cb = 4 * hg + 2 * kh;
    const float wl0 = (cb     < Hh) ? W_lin[cb]     : 0.f;
    const float wl1 = (cb + 1 < Hh) ? W_lin[cb + 1] : 0.f;
    float c1[2] = {}, c2[2] = {};

    const int grow = blockIdx.x * 32 + lane;
    float xv = 0.f, blin = 0.f;
    const bool tail = (w == NWARP - 1);
    if (tail) {
        blin = b_lin[0];
        float x0 = xin[grow * T_IN];
        __half xh = __float2half(x0);
        s->B1[0][0][lane][Hh] = xh;
        s->B1[0][1][lane][Hh] = __float2half(x0 - __half2float(xh));
        xv = xin[grow * T_IN + 1];
    }

    // ---- phase helpers ----
    auto do_mma1 = [&](int pb) {
        #pragma unroll
        for (int nt = 0; nt < 4; ++nt) {
            float d0 = bA0, d1 = bA0, d2 = bA1, d3 = bA1;
            #pragma unroll
            for (int kc = 0; kc < 2; ++kc) {
                int kG = (2 * kh + kc) * 16 + q2;
                const __half* bh = &s->B1[pb][0][nt * 8 + g][kG];
                const __half* bl = &s->B1[pb][1][nt * 8 + g][kG];
                unsigned b0h = *reinterpret_cast<const unsigned*>(bh);
                unsigned b1h = *reinterpret_cast<const unsigned*>(bh + 8);
                unsigned b0l = *reinterpret_cast<const unsigned*>(bl);
                unsigned b1l = *reinterpret_cast<const unsigned*>(bl + 8);
                MMA_F16(d0,d1,d2,d3, A1[kc][0],A1[kc][1],A1[kc][2],A1[kc][3], b0h,b1h);
                MMA_F16(d0,d1,d2,d3, A1[kc][0],A1[kc][1],A1[kc][2],A1[kc][3], b0l,b1l);
            }
            *reinterpret_cast<float2*>(&s->XG[hg][0][kh][g][nt * 8 + q2])     = make_float2(d0, d1);
            *reinterpret_cast<float2*>(&s->XG[hg][0][kh][g + 8][nt * 8 + q2]) = make_float2(d2, d3);
        }
    };
    auto do_mma2 = [&](int pb) {
        const int nkc = kh ? 3 : 4;
        #pragma unroll
        for (int nt = 0; nt < 4; ++nt) {
            float d0 = bB0, d1 = bB0, d2 = bB1, d3 = bB1;
            for (int kc = 0; kc < nkc; ++kc) {
                int kG = (k2b + kc) * 16 + q2;
                const __half* bh = &s->B2[pb][0][nt * 8 + g][kG];
                const __half* bl = &s->B2[pb][1][nt * 8 + g][kG];
                unsigned b0h = *reinterpret_cast<const unsigned*>(bh);
                unsigned b1h = *reinterpret_cast<const unsigned*>(bh + 8);
                unsigned b0l = *reinterpret_cast<const unsigned*>(bl);
                unsigned b1l = *reinterpret_cast<const unsigned*>(bl + 8);
                MMA_F16(d0,d1,d2,d3, A2[kc][0],A2[kc][1],A2[kc][2],A2[kc][3], b0h,b1h);
                MMA_F16(d0,d1,d2,d3, A2[kc][0],A2[kc][1],A2[kc][2],A2[kc][3], b0l,b1l);
            }
            *reinterpret_cast<float2*>(&s->XG[hg][1][kh][g][nt * 8 + q2])     = make_float2(d0, d1);
            *reinterpret_cast<float2*>(&s->XG[hg][1][kh][g + 8][nt * 8 + q2]) = make_float2(d2, d3);
        }
    };
    auto do_pw1 = [&](int pbB1, int pbB2) {
        float hv[2];
        #pragma unroll
        for (int j = 0; j < 2; ++j) {
            int r = 4 * (2 * kh + j);
            float gi = s->XG[hg][0][0][r+0][lane] + s->XG[hg][0][1][r+0][lane];
            float gf = s->XG[hg][0][0][r+1][lane] + s->XG[hg][0][1][r+1][lane];
            float gg = s->XG[hg][0][0][r+2][lane] + s->XG[hg][0][1][r+2][lane];
            float go = s->XG[hg][0][0][r+3][lane] + s->XG[hg][0][1][r+3][lane];
            float cn = sigA(gf) * c1[j] + sigA(gi) * tanhA(gg);
            c1[j] = cn;
            hv[j] = sigA(go) * tanhA(cn);
        }
        __half h0 = __float2half(hv[0]), h1 = __float2half(hv[1]);
        unsigned hi = (unsigned)__half_as_ushort(h0) | ((unsigned)__half_as_ushort(h1) << 16);
        unsigned lo = mkh2(hv[0] - __half2float(h0), hv[1] - __half2float(h1));
        *reinterpret_cast<unsigned*>(&s->B1[pbB1][0][lane][cb]) = hi;
        *reinterpret_cast<unsigned*>(&s->B1[pbB1][1][lane][cb]) = lo;
        *reinterpret_cast<unsigned*>(&s->B2[pbB2][0][lane][cb]) = hi;
        *reinterpret_cast<unsigned*>(&s->B2[pbB2][1][lane][cb]) = lo;
    };
    auto do_pw2 = [&](int pbB2, int php) {
        float hv[2];
        #pragma unroll
        for (int j = 0; j < 2; ++j) {
            int r = 4 * (2 * kh + j);
            float gi = s->XG[hg][1][0][r+0][lane] + s->XG[hg][1][1][r+0][lane];
            float gf = s->XG[hg][1][0][r+1][lane] + s->XG[hg][1][1][r+1][lane];
            float gg = s->XG[hg][1][0][r+2][lane] + s->XG[hg][1][1][r+2][lane];
            float go = s->XG[hg][1][0][r+3][lane] + s->XG[hg][1][1][r+3][lane];
            float cn = sigA(gf) * c2[j] + sigA(gi) * tanhA(gg);
            c2[j] = cn;
            hv[j] = sigA(go) * tanhA(cn);
        }
        __half h0 = __float2half(hv[0]), h1 = __float2half(hv[1]);
        unsigned hi = (unsigned)__half_as_ushort(h0) | ((unsigned)__half_as_ushort(h1) << 16);
        unsigned lo = mkh2(hv[0] - __half2float(h0), hv[1] - __half2float(h1));
        *reinterpret_cast<unsigned*>(&s->B2[pbB2][0][lane][52 + cb]) = hi;
        *reinterpret_cast<unsigned*>(&s->B2[pbB2][1][lane][52 + cb]) = lo;
        s->PH[php][w][lane] = wl0 * hv[0] + wl1 * hv[1];
    };
    auto do_head = [&](int php, int tt) -> float {
        float o = blin;
        #pragma unroll
        for (int ww = 0; ww < NWARP; ++ww) o += s->PH[php][ww][lane];
        out[grow * T_TOT + tt] = o;
        return o;
    };
    auto stage_x = [&](int pb, float xs) {
        __half xh = __float2half(xs);
        s->B1[pb][0][lane][Hh] = xh;
        s->B1[pb][1][lane][Hh] = __float2half(xs - __half2float(xh));
    };

    __syncthreads();

    // ---- prologue: MMA1(0), pw1(0), stage x(1) ----
    do_mma1(0);
    PAIRBAR();
    do_pw1(1, 0);
    if (tail) { stage_x(1, xv); xv = xin[grow * T_IN + 2]; }
    __syncthreads();

    // ---- pipelined teacher loop: t = 0 .. T_IN-2 ----
    for (int t = 0; t < T_IN - 1; ++t) {
        const int p = t & 1;
        do_mma2(p);        // layer2 of step t
        do_mma1(p ^ 1);    // layer1 of step t+1
        PAIRBAR();
        do_pw2(p ^ 1, p);  // h2new(t) -> B2[p^1]; PH[p]
        do_pw1(p, p ^ 1);  // h1new(t+1) -> B1[p], B2[p^1]
        if (tail) {
            if (t >= 1) do_head(p ^ 1, t - 1);
            if (t + 2 < T_IN) {
                stage_x(p, xv);
                if (t + 3 < T_IN) xv = xin[grow * T_IN + t + 3];
            }
        }
        __syncthreads();
    }

    // ---- sequential epilogue: t = T_IN-1 .. T_TOT-1 (feedback phase) ----
    for (int t = T_IN - 1; t < T_TOT; ++t) {
        const int p = t & 1;
        do_mma2(p);
        PAIRBAR();
        do_pw2(p ^ 1, p);
        __syncthreads();
        if (tail) {
            if (t == T_IN - 1) do_head(p ^ 1, t - 1);   // pending out(T_IN-2)
            float o = do_head(p, t);
            if (t + 1 < T_TOT) stage_x(p ^ 1, o);       // x(t+1) = out(t)
        }
        __syncthreads();
        if (t + 1 < T_TOT) {
            do_mma1(p ^ 1);
            PAIRBAR();
            do_pw1(p, p ^ 1);
            __syncthreads();
        }
    }
}

extern "C" void kernel_launch(void* const* d_in, const int* in_sizes, int n_in,
                              void* d_out, int out_size) {
    (void)in_sizes; (void)n_in; (void)out_size;
    cudaFuncSetAttribute(lstm_mma_kernel, cudaFuncAttributeMaxDynamicSharedMemorySize, SMEM_TOTAL);
    lstm_mma_kernel<<<NCTA, NTHR, SMEM_TOTAL>>>(
        (const float*)d_in[0],   // inputs [B, T]
        (const float*)d_in[1],   // W_ih1 [204,1]
        (const float*)d_in[2],   // W_hh1 [204,51]
        (const float*)d_in[3],   // b_ih1 [204]
        (const float*)d_in[4],   // b_hh1 [204]
        (const float*)d_in[5],   // W_ih2 [204,51]
        (const float*)d_in[6],   // W_hh2 [204,51]
        (const float*)d_in[7],   // b_ih2 [204]
        (const float*)d_in[8],   // b_hh2 [204]
        (const float*)d_in[9],   // W_lin [1,51]
        (const float*)d_in[10],  // b_lin [1]
        (float*)d_out);          // out [B, 1100]
}

// round 14
// speedup vs baseline: 5.1460x; 1.5817x over previous
#include <cuda_runtime.h>
#include <cuda_fp16.h>

// Sequence_53300544143404 R14: R13 pipeline + halved smem bytes.
// (a) states single fp16 (B-lo combo dropped): halves MMAs + B-fragment bytes;
// (b) partial-gate exchange (XG) in fp16: halves exchange bytes.
// Predicted rel_err 3-5e-4 (measured amplification ~0.5x). Teacher phase
// pipelined (MMA2(t)+MMA1(t+1) / pw2(t)+pw1(t+1)), lagged head; sequential
// feedback epilogue. 128 CTAs x 832 threads (13 pairs x 2 k-halves).

#define Hh    51
#define T_IN  1000
#define T_TOT 1100
#define NPAIR 13
#define NWARP 26
#define NTHR  832
#define NCTA  128
#define SD1   72
#define SD2   120

struct S {
    __half B1[2][32][SD1];           // [pp][n][k] k:0..50 h1, 51 x
    __half B2[2][32][SD2];           // k:0..50 h1new, 52..102 h2
    __half XG[NPAIR][2][2][16][36];  // [pair][layer][khalf][gaterow][n] fp16
    float  PH[2][NWARP][32];         // double-buffered W_lin partials
};
#define SMEM_TOTAL ((int)sizeof(S))

#define MMA_F16(d0,d1,d2,d3, a0,a1,a2,a3, b0,b1) \
    asm volatile("mma.sync.aligned.m16n8k16.row.col.f32.f16.f16.f32 " \
        "{%0,%1,%2,%3}, {%4,%5,%6,%7}, {%8,%9}, {%0,%1,%2,%3};" \
        : "+f"(d0),"+f"(d1),"+f"(d2),"+f"(d3) \
        : "r"(a0),"r"(a1),"r"(a2),"r"(a3), "r"(b0),"r"(b1))
#define PAIRBAR() asm volatile("bar.sync %0, 64;" :: "r"(hg + 1) : "memory")

__device__ __forceinline__ float tanhA(float x) {
    float r; asm("tanh.approx.f32 %0, %1;" : "=f"(r) : "f"(x)); return r;
}
__device__ __forceinline__ float sigA(float x) {
    return fmaf(tanhA(0.5f * x), 0.5f, 0.5f);
}
__device__ __forceinline__ unsigned mkh2(float v0, float v1) {
    __half h0 = __float2half(v0), h1 = __float2half(v1);
    return (unsigned)__half_as_ushort(h0) | ((unsigned)__half_as_ushort(h1) << 16);
}
__device__ __forceinline__ float wf1(const float* Wih1, const float* Whh1, int R, int k) {
    int h = R >> 2, g = R & 3;
    if (h >= Hh) return 0.f;
    if (k < Hh)  return Whh1[(g * Hh + h) * Hh + k];
    if (k == Hh) return Wih1[g * Hh + h];
    return 0.f;
}
__device__ __forceinline__ float wf2(const float* Wih2, const float* Whh2, int R, int k) {
    int h = R >> 2, g = R & 3;
    if (h >= Hh) return 0.f;
    if (k < Hh) return Wih2[(g * Hh + h) * Hh + k];
    if (k >= 52 && k < 52 + Hh) return Whh2[(g * Hh + h) * Hh + (k - 52)];
    return 0.f;
}
__device__ __forceinline__ float bias_(const float* bi, const float* bh, int R) {
    int h = R >> 2, g = R & 3;
    if (h >= Hh) return 0.f;
    return bi[g * Hh + h] + bh[g * Hh + h];
}

extern __shared__ __align__(16) char smem_raw[];

__global__ __launch_bounds__(NTHR, 1)
void lstm_mma_kernel(const float* __restrict__ xin,
                     const float* __restrict__ W_ih1, const float* __restrict__ W_hh1,
                     const float* __restrict__ b_ih1, const float* __restrict__ b_hh1,
                     const float* __restrict__ W_ih2, const float* __restrict__ W_hh2,
                     const float* __restrict__ b_ih2, const float* __restrict__ b_hh2,
                     const float* __restrict__ W_lin, const float* __restrict__ b_lin,
                     float* __restrict__ out)
{
    S* s = reinterpret_cast<S*>(smem_raw);
    const int tid  = threadIdx.x;
    const int lane = tid & 31;
    const int w    = tid >> 5;
    const int hg   = w >> 1;
    const int kh   = w & 1;
    const int g    = lane >> 2;
    const int q2   = (lane & 3) * 2;

    for (int i = tid; i < (int)(sizeof(s->B1) + sizeof(s->B2)) / 4; i += NTHR)
        reinterpret_cast<unsigned*>(s->B1)[i] = 0u;

    // A fragments (fp16)
    const int R0 = 16 * hg + g, R1 = R0 + 8;
    unsigned A1[2][4], A2[4][4];
    #pragma unroll
    for (int kc = 0; kc < 2; ++kc) {
        int kb = (2 * kh + kc) * 16 + q2;
        A1[kc][0] = mkh2(wf1(W_ih1,W_hh1,R0,kb),   wf1(W_ih1,W_hh1,R0,kb+1));
        A1[kc][1] = mkh2(wf1(W_ih1,W_hh1,R1,kb),   wf1(W_ih1,W_hh1,R1,kb+1));
        A1[kc][2] = mkh2(wf1(W_ih1,W_hh1,R0,kb+8), wf1(W_ih1,W_hh1,R0,kb+9));
        A1[kc][3] = mkh2(wf1(W_ih1,W_hh1,R1,kb+8), wf1(W_ih1,W_hh1,R1,kb+9));
    }
    const int k2b = kh ? 4 : 0;
    #pragma unroll
    for (int kc = 0; kc < 4; ++kc) {
        int kb = (k2b + kc) * 16 + q2;
        A2[kc][0] = mkh2(wf2(W_ih2,W_hh2,R0,kb),   wf2(W_ih2,W_hh2,R0,kb+1));
        A2[kc][1] = mkh2(wf2(W_ih2,W_hh2,R1,kb),   wf2(W_ih2,W_hh2,R1,kb+1));
        A2[kc][2] = mkh2(wf2(W_ih2,W_hh2,R0,kb+8), wf2(W_ih2,W_hh2,R0,kb+9));
        A2[kc][3] = mkh2(wf2(W_ih2,W_hh2,R1,kb+8), wf2(W_ih2,W_hh2,R1,kb+9));
    }
    const float bA0 = kh ? 0.f : bias_(b_ih1, b_hh1, R0);
    const float bA1 = kh ? 0.f : bias_(b_ih1, b_hh1, R1);
    const float bB0 = kh ? 0.f : bias_(b_ih2, b_hh2, R0);
    const float bB1 = kh ? 0.f : bias_(b_ih2, b_hh2, R1);

    const int cb = 4 * hg + 2 * kh;
    const float wl0 = (cb     < Hh) ? W_lin[cb]     : 0.f;
    const float wl1 = (cb + 1 < Hh) ? W_lin[cb + 1] : 0.f;
    float c1[2] = {}, c2[2] = {};

    const int grow = blockIdx.x * 32 + lane;
    float xv = 0.f, blin = 0.f;
    const bool tail = (w == NWARP - 1);
    if (tail) {
        blin = b_lin[0];
        s->B1[0][lane][Hh] = __float2half(xin[grow * T_IN]);
        xv = xin[grow * T_IN + 1];
    }

    // ---- phase helpers ----
    auto do_mma1 = [&](int pb) {
        #pragma unroll
        for (int nt = 0; nt < 4; ++nt) {
            float d0 = bA0, d1 = bA0, d2 = bA1, d3 = bA1;
            #pragma unroll
            for (int kc = 0; kc < 2; ++kc) {
                int kG = (2 * kh + kc) * 16 + q2;
                const __half* bh = &s->B1[pb][nt * 8 + g][kG];
                unsigned b0 = *reinterpret_cast<const unsigned*>(bh);
                unsigned b1 = *reinterpret_cast<const unsigned*>(bh + 8);
                MMA_F16(d0,d1,d2,d3, A1[kc][0],A1[kc][1],A1[kc][2],A1[kc][3], b0,b1);
            }
            *reinterpret_cast<__half2*>(&s->XG[hg][0][kh][g][nt * 8 + q2])     = __floats2half2_rn(d0, d1);
            *reinterpret_cast<__half2*>(&s->XG[hg][0][kh][g + 8][nt * 8 + q2]) = __floats2half2_rn(d2, d3);
        }
    };
    auto do_mma2 = [&](int pb) {
        const int nkc = kh ? 3 : 4;
        #pragma unroll
        for (int nt = 0; nt < 4; ++nt) {
            float d0 = bB0, d1 = bB0, d2 = bB1, d3 = bB1;
            for (int kc = 0; kc < nkc; ++kc) {
                int kG = (k2b + kc) * 16 + q2;
                const __half* bh = &s->B2[pb][nt * 8 + g][kG];
                unsigned b0 = *reinterpret_cast<const unsigned*>(bh);
                unsigned b1 = *reinterpret_cast<const unsigned*>(bh + 8);
                MMA_F16(d0,d1,d2,d3, A2[kc][0],A2[kc][1],A2[kc][2],A2[kc][3], b0,b1);
            }
            *reinterpret_cast<__half2*>(&s->XG[hg][1][kh][g][nt * 8 + q2])     = __floats2half2_rn(d0, d1);
            *reinterpret_cast<__half2*>(&s->XG[hg][1][kh][g + 8][nt * 8 + q2]) = __floats2half2_rn(d2, d3);
        }
    };
    auto do_pw1 = [&](int pbB1, int pbB2) {
        float hv[2];
        #pragma unroll
        for (int j = 0; j < 2; ++j) {
            int r = 4 * (2 * kh + j);
            float gi = __half2float(s->XG[hg][0][0][r+0][lane]) + __half2float(s->XG[hg][0][1][r+0][lane]);
            float gf = __half2float(s->XG[hg][0][0][r+1][lane]) + __half2float(s->XG[hg][0][1][r+1][lane]);
            float gg = __half2float(s->XG[hg][0][0][r+2][lane]) + __half2float(s->XG[hg][0][1][r+2][lane]);
            float go = __half2float(s->XG[hg][0][0][r+3][lane]) + __half2float(s->XG[hg][0][1][r+3][lane]);
            float cn = sigA(gf) * c1[j] + sigA(gi) * tanhA(gg);
            c1[j] = cn;
            hv[j] = sigA(go) * tanhA(cn);
        }
        unsigned hi = mkh2(hv[0], hv[1]);
        // (pair hg=12,kh=1 writes col 51 = 0 here; x-stage overwrites it after, same thread)
        *reinterpret_cast<unsigned*>(&s->B1[pbB1][lane][cb]) = hi;
        *reinterpret_cast<unsigned*>(&s->B2[pbB2][lane][cb]) = hi;
    };
    auto do_pw2 = [&](int pbB2, int php) {
        float hv[2];
        #pragma unroll
        for (int j = 0; j < 2; ++j) {
            int r = 4 * (2 * kh + j);
            float gi = __half2float(s->XG[hg][1][0][r+0][lane]) + __half2float(s->XG[hg][1][1][r+0][lane]);
            float gf = __half2float(s->XG[hg][1][0][r+1][lane]) + __half2float(s->XG[hg][1][1][r+1][lane]);
            float gg = __half2float(s->XG[hg][1][0][r+2][lane]) + __half2float(s->XG[hg][1][1][r+2][lane]);
            float go = __half2float(s->XG[hg][1][0][r+3][lane]) + __half2float(s->XG[hg][1][1][r+3][lane]);
            float cn = sigA(gf) * c2[j] + sigA(gi) * tanhA(gg);
            c2[j] = cn;
            hv[j] = sigA(go) * tanhA(cn);
        }
        *reinterpret_cast<unsigned*>(&s->B2[pbB2][lane][52 + cb]) = mkh2(hv[0], hv[1]);
        s->PH[php][w][lane] = wl0 * hv[0] + wl1 * hv[1];
    };
    auto do_head = [&](int php, int tt) -> float {
        float o = blin;
        #pragma unroll
        for (int ww = 0; ww < NWARP; ++ww) o += s->PH[php][ww][lane];
        out[grow * T_TOT + tt] = o;
        return o;
    };
    auto stage_x = [&](int pb, float xs) {
        s->B1[pb][lane][Hh] = __float2half(xs);
    };

    __syncthreads();

    // ---- prologue: MMA1(0), pw1(0), stage x(1) ----
    do_mma1(0);
    PAIRBAR();
    do_pw1(1, 0);
    if (tail) { stage_x(1, xv); xv = xin[grow * T_IN + 2]; }
    __syncthreads();

    // ---- pipelined teacher loop: t = 0 .. T_IN-2 ----
    for (int t = 0; t < T_IN - 1; ++t) {
        const int p = t & 1;
        do_mma2(p);        // layer2 of step t
        do_mma1(p ^ 1);    // layer1 of step t+1
        PAIRBAR();
        do_pw2(p ^ 1, p);  // h2new(t) -> B2[p^1]; PH[p]
        do_pw1(p, p ^ 1);  // h1new(t+1) -> B1[p], B2[p^1]
        if (tail) {
            if (t >= 1) do_head(p ^ 1, t - 1);
            if (t + 2 < T_IN) {
                stage_x(p, xv);
                if (t + 3 < T_IN) xv = xin[grow * T_IN + t + 3];
            }
        }
        __syncthreads();
    }

    // ---- sequential epilogue: t = T_IN-1 .. T_TOT-1 (feedback phase) ----
    for (int t = T_IN - 1; t < T_TOT; ++t) {
        const int p = t & 1;
        do_mma2(p);
        PAIRBAR();
        do_pw2(p ^ 1, p);
        __syncthreads();
        if (tail) {
            if (t == T_IN - 1) do_head(p ^ 1, t - 1);   // pending out(T_IN-2)
            float o = do_head(p, t);
            if (t + 1 < T_TOT) stage_x(p ^ 1, o);       // x(t+1) = out(t)
        }
        __syncthreads();
        if (t + 1 < T_TOT) {
            do_mma1(p ^ 1);
            PAIRBAR();
            do_pw1(p, p ^ 1);
            __syncthreads();
        }
    }
}

extern "C" void kernel_launch(void* const* d_in, const int* in_sizes, int n_in,
                              void* d_out, int out_size) {
    (void)in_sizes; (void)n_in; (void)out_size;
    cudaFuncSetAttribute(lstm_mma_kernel, cudaFuncAttributeMaxDynamicSharedMemorySize, SMEM_TOTAL);
    lstm_mma_kernel<<<NCTA, NTHR, SMEM_TOTAL>>>(
        (const float*)d_in[0],   // inputs [B, T]
        (const float*)d_in[1],   // W_ih1 [204,1]
        (const float*)d_in[2],   // W_hh1 [204,51]
        (const float*)d_in[3],   // b_ih1 [204]
        (const float*)d_in[4],   // b_hh1 [204]
        (const float*)d_in[5],   // W_ih2 [204,51]
        (const float*)d_in[6],   // W_hh2 [204,51]
        (const float*)d_in[7],   // b_ih2 [204]
        (const float*)d_in[8],   // b_hh2 [204]
        (const float*)d_in[9],   // W_lin [1,51]
        (const float*)d_in[10],  // b_lin [1]
        (float*)d_out);          // out [B, 1100]
}

// round 15
// speedup vs baseline: 6.0923x; 1.1839x over previous
#include <cuda_runtime.h>
#include <cuda_fp16.h>

// Sequence_53300544143404 R15: layer-split warp pairs — zero exchange traffic.
// Warps 0-12: layer1 tiles (16 gate rows, full K=64); warps 13-25: layer2
// (full K=112). Accumulators complete per warp -> warp-private f32 G tile,
// __syncwarp, own pw. One CTA barrier per teacher step. Head + x staging on
// warp 12 (program-ordered with its own col-51 write). fp16 weights/states,
// tanh.approx, pipelined teacher loop + sequential feedback epilogue.
// 128 CTAs x 832 threads.

#define Hh    51
#define T_IN  1000
#define T_TOT 1100
#define NW1   13
#define NWARP 26
#define NTHR  832
#define NCTA  128
#define SD1   72    // B1 row stride (halves): conflict-free (4g+q)
#define SD2   120   // B2 row stride (halves): conflict-free (28g+q)

struct S {
    __half B1[2][32][SD1];    // [pp][n][k] k:0..50 h1, 51 x, rest 0
    __half B2[2][32][SD2];    // k:0..50 h1new, 51 zero, 52..102 h2, rest 0
    float  G[NWARP][16][36];  // warp-private gate tiles (col-parity swizzled)
    float  PH[2][NW1][32];    // double-buffered W_lin partials (L2 warps)
};
#define SMEM_TOTAL ((int)sizeof(S))

#define MMA_F16(d0,d1,d2,d3, a0,a1,a2,a3, b0,b1) \
    asm volatile("mma.sync.aligned.m16n8k16.row.col.f32.f16.f16.f32 " \
        "{%0,%1,%2,%3}, {%4,%5,%6,%7}, {%8,%9}, {%0,%1,%2,%3};" \
        : "+f"(d0),"+f"(d1),"+f"(d2),"+f"(d3) \
        : "r"(a0),"r"(a1),"r"(a2),"r"(a3), "r"(b0),"r"(b1))

__device__ __forceinline__ float tanhA(float x) {
    float r; asm("tanh.approx.f32 %0, %1;" : "=f"(r) : "f"(x)); return r;
}
__device__ __forceinline__ float sigA(float x) {
    return fmaf(tanhA(0.5f * x), 0.5f, 0.5f);
}
__device__ __forceinline__ unsigned mkh2(float v0, float v1) {
    __half h0 = __float2half(v0), h1 = __float2half(v1);
    return (unsigned)__half_as_ushort(h0) | ((unsigned)__half_as_ushort(h1) << 16);
}
__device__ __forceinline__ float wf1(const float* Wih1, const float* Whh1, int R, int k) {
    int h = R >> 2, g = R & 3;
    if (h >= Hh) return 0.f;
    if (k < Hh)  return Whh1[(g * Hh + h) * Hh + k];
    if (k == Hh) return Wih1[g * Hh + h];
    return 0.f;
}
__device__ __forceinline__ float wf2(const float* Wih2, const float* Whh2, int R, int k) {
    int h = R >> 2, g = R & 3;
    if (h >= Hh) return 0.f;
    if (k < Hh) return Wih2[(g * Hh + h) * Hh + k];
    if (k >= 52 && k < 52 + Hh) return Whh2[(g * Hh + h) * Hh + (k - 52)];
    return 0.f;
}
__device__ __forceinline__ float bias_(const float* bi, const float* bh, int R) {
    int h = R >> 2, g = R & 3;
    if (h >= Hh) return 0.f;
    return bi[g * Hh + h] + bh[g * Hh + h];
}

extern __shared__ __align__(16) char smem_raw[];

__global__ __launch_bounds__(NTHR, 1)
void lstm_mma_kernel(const float* __restrict__ xin,
                     const float* __restrict__ W_ih1, const float* __restrict__ W_hh1,
                     const float* __restrict__ b_ih1, const float* __restrict__ b_hh1,
                     const float* __restrict__ W_ih2, const float* __restrict__ W_hh2,
                     const float* __restrict__ b_ih2, const float* __restrict__ b_hh2,
                     const float* __restrict__ W_lin, const float* __restrict__ b_lin,
                     float* __restrict__ out)
{
    S* s = reinterpret_cast<S*>(smem_raw);
    const int tid  = threadIdx.x;
    const int lane = tid & 31;
    const int w    = tid >> 5;
    const bool isL1 = (w < NW1);
    const int wl   = isL1 ? w : w - NW1;   // weight-tile index 0..12
    const int g    = lane >> 2;            // mma groupID 0..7
    const int q2   = (lane & 3) * 2;
    const int sw   = g & 1;                // G column-parity swizzle

    for (int i = tid; i < (int)(sizeof(s->B1) + sizeof(s->B2)) / 4; i += NTHR)
        reinterpret_cast<unsigned*>(s->B1)[i] = 0u;

    // A fragments (fp16, full K for my layer)
    const int R0 = 16 * wl + g, R1 = R0 + 8;
    unsigned A[7][4];
    float bR0, bR1;
    if (isL1) {
        #pragma unroll
        for (int kc = 0; kc < 4; ++kc) {
            int kb = kc * 16 + q2;
            A[kc][0] = mkh2(wf1(W_ih1,W_hh1,R0,kb),   wf1(W_ih1,W_hh1,R0,kb+1));
            A[kc][1] = mkh2(wf1(W_ih1,W_hh1,R1,kb),   wf1(W_ih1,W_hh1,R1,kb+1));
            A[kc][2] = mkh2(wf1(W_ih1,W_hh1,R0,kb+8), wf1(W_ih1,W_hh1,R0,kb+9));
            A[kc][3] = mkh2(wf1(W_ih1,W_hh1,R1,kb+8), wf1(W_ih1,W_hh1,R1,kb+9));
        }
        bR0 = bias_(b_ih1, b_hh1, R0); bR1 = bias_(b_ih1, b_hh1, R1);
    } else {
        #pragma unroll
        for (int kc = 0; kc < 7; ++kc) {
            int kb = kc * 16 + q2;
            A[kc][0] = mkh2(wf2(W_ih2,W_hh2,R0,kb),   wf2(W_ih2,W_hh2,R0,kb+1));
            A[kc][1] = mkh2(wf2(W_ih2,W_hh2,R1,kb),   wf2(W_ih2,W_hh2,R1,kb+1));
            A[kc][2] = mkh2(wf2(W_ih2,W_hh2,R0,kb+8), wf2(W_ih2,W_hh2,R0,kb+9));
            A[kc][3] = mkh2(wf2(W_ih2,W_hh2,R1,kb+8), wf2(W_ih2,W_hh2,R1,kb+9));
        }
        bR0 = bias_(b_ih2, b_hh2, R0); bR1 = bias_(b_ih2, b_hh2, R1);
    }

    // pointwise role: my 4 h = 4wl..4wl+3, n = lane
    const int cb = 4 * wl;
    float wl_[4];
    #pragma unroll
    for (int j = 0; j < 4; ++j)
        wl_[j] = (cb + j < Hh) ? W_lin[cb + j] : 0.f;
    float c_[4] = {};

    const int grow = blockIdx.x * 32 + lane;
    const bool hd = (w == 12);   // head + x-stager warp (L1, owns col 48..51)
    float xv = 0.f, blin = 0.f;
    if (hd) {
        blin = b_lin[0];
        s->B1[0][lane][Hh] = __float2half(xin[grow * T_IN]);
        xv = xin[grow * T_IN + 1];
    }

    // ---- phase helpers ----
    auto mma_l1 = [&](int pb) {
        #pragma unroll
        for (int nt = 0; nt < 4; ++nt) {
            float d0 = bR0, d1 = bR0, d2 = bR1, d3 = bR1;
            #pragma unroll
            for (int kc = 0; kc < 4; ++kc) {
                const __half* bp = &s->B1[pb][nt * 8 + g][kc * 16 + q2];
                unsigned b0 = *reinterpret_cast<const unsigned*>(bp);
                unsigned b1 = *reinterpret_cast<const unsigned*>(bp + 8);
                MMA_F16(d0,d1,d2,d3, A[kc][0],A[kc][1],A[kc][2],A[kc][3], b0,b1);
            }
            int c0 = nt * 8 + q2;
            s->G[w][g][c0 + sw] = d0;     s->G[w][g][c0 + 1 - sw] = d1;
            s->G[w][g + 8][c0 + sw] = d2; s->G[w][g + 8][c0 + 1 - sw] = d3;
        }
    };
    auto mma_l2 = [&](int pb) {
        #pragma unroll
        for (int nt = 0; nt < 4; ++nt) {
            float d0 = bR0, d1 = bR0, d2 = bR1, d3 = bR1;
            #pragma unroll
            for (int kc = 0; kc < 7; ++kc) {
                const __half* bp = &s->B2[pb][nt * 8 + g][kc * 16 + q2];
                unsigned b0 = *reinterpret_cast<const unsigned*>(bp);
                unsigned b1 = *reinterpret_cast<const unsigned*>(bp + 8);
                MMA_F16(d0,d1,d2,d3, A[kc][0],A[kc][1],A[kc][2],A[kc][3], b0,b1);
            }
            int c0 = nt * 8 + q2;
            s->G[w][g][c0 + sw] = d0;     s->G[w][g][c0 + 1 - sw] = d1;
            s->G[w][g + 8][c0 + sw] = d2; s->G[w][g + 8][c0 + 1 - sw] = d3;
        }
    };
    auto pw_l1 = [&](int pbB1, int pbB2) {
        float hv[4];
        #pragma unroll
        for (int j = 0; j < 4; ++j) {
            float gi = s->G[w][4*j+0][lane];
            float gf = s->G[w][4*j+1][lane ^ 1];
            float gg = s->G[w][4*j+2][lane];
            float go = s->G[w][4*j+3][lane ^ 1];
            float cn = sigA(gf) * c_[j] + sigA(gi) * tanhA(gg);
            c_[j] = cn;
            hv[j] = sigA(go) * tanhA(cn);
        }
        uint2 u = make_uint2(mkh2(hv[0], hv[1]), mkh2(hv[2], hv[3]));
        // (warp 12 writes col 51 = 0 here; its own stage_x overwrites after)
        *reinterpret_cast<uint2*>(&s->B1[pbB1][lane][cb]) = u;
        *reinterpret_cast<uint2*>(&s->B2[pbB2][lane][cb]) = u;
    };
    auto pw_l2 = [&](int pbB2, int php) {
        float hv[4];
        #pragma unroll
        for (int j = 0; j < 4; ++j) {
            float gi = s->G[w][4*j+0][lane];
            float gf = s->G[w][4*j+1][lane ^ 1];
            float gg = s->G[w][4*j+2][lane];
            float go = s->G[w][4*j+3][lane ^ 1];
            float cn = sigA(gf) * c_[j] + sigA(gi) * tanhA(gg);
            c_[j] = cn;
            hv[j] = sigA(go) * tanhA(cn);
        }
        uint2 u = make_uint2(mkh2(hv[0], hv[1]), mkh2(hv[2], hv[3]));
        *reinterpret_cast<uint2*>(&s->B2[pbB2][lane][52 + cb]) = u;
        s->PH[php][wl][lane] = wl_[0]*hv[0] + wl_[1]*hv[1] + wl_[2]*hv[2] + wl_[3]*hv[3];
    };
    auto do_head = [&](int php, int tt) -> float {
        float o = blin;
        #pragma unroll
        for (int ww = 0; ww < NW1; ++ww) o += s->PH[php][ww][lane];
        out[grow * T_TOT + tt] = o;
        return o;
    };
    auto stage_x = [&](int pb, float xs) {
        s->B1[pb][lane][Hh] = __float2half(xs);
    };

    __syncthreads();

    // ---- prologue: layer1 of step 0; stage x(1) ----
    if (isL1) {
        mma_l1(0);
        __syncwarp();
        pw_l1(1, 0);
        if (hd) { stage_x(1, xv); xv = xin[grow * T_IN + 2]; }
    }
    __syncthreads();

    // ---- pipelined teacher loop: t = 0 .. T_IN-2 ----
    for (int t = 0; t < T_IN - 1; ++t) {
        const int p = t & 1;
        if (isL1) {
            mma_l1(p ^ 1);          // layer1 of step t+1
            __syncwarp();
            pw_l1(p, p ^ 1);        // h1new(t+1) -> B1[p], B2[p^1]
            if (hd) {
                if (t >= 1) do_head(p ^ 1, t - 1);
                if (t + 2 < T_IN) {
                    stage_x(p, xv);
                    if (t + 3 < T_IN) xv = xin[grow * T_IN + t + 3];
                }
            }
        } else {
            mma_l2(p);              // layer2 of step t
            __syncwarp();
            pw_l2(p ^ 1, p);        // h2new(t) -> B2[p^1]; PH[p]
        }
        __syncthreads();
    }

    // ---- sequential feedback epilogue: t = T_IN-1 .. T_TOT-1 ----
    for (int t = T_IN - 1; t < T_TOT; ++t) {
        const int p = t & 1;
        if (!isL1) {
            mma_l2(p);
            __syncwarp();
            pw_l2(p ^ 1, p);
        }
        __syncthreads();
        if (hd) {
            if (t == T_IN - 1) do_head(p ^ 1, t - 1);   // pending out(T_IN-2)
            float o = do_head(p, t);
            if (t + 1 < T_TOT) stage_x(p ^ 1, o);       // x(t+1) = out(t)
        }
        __syncthreads();
        if (t + 1 < T_TOT) {
            if (isL1) {
                mma_l1(p ^ 1);
                __syncwarp();
                pw_l1(p, p ^ 1);
            }
            __syncthreads();
        }
    }
}

extern "C" void kernel_launch(void* const* d_in, const int* in_sizes, int n_in,
                              void* d_out, int out_size) {
    (void)in_sizes; (void)n_in; (void)out_size;
    cudaFuncSetAttribute(lstm_mma_kernel, cudaFuncAttributeMaxDynamicSharedMemorySize, SMEM_TOTAL);
    lstm_mma_kernel<<<NCTA, NTHR, SMEM_TOTAL>>>(
        (const float*)d_in[0],   // inputs [B, T]
        (const float*)d_in[1],   // W_ih1 [204,1]
        (const float*)d_in[2],   // W_hh1 [204,51]
        (const float*)d_in[3],   // b_ih1 [204]
        (const float*)d_in[4],   // b_hh1 [204]
        (const float*)d_in[5],   // W_ih2 [204,51]
        (const float*)d_in[6],   // W_hh2 [204,51]
        (const float*)d_in[7],   // b_ih2 [204]
        (const float*)d_in[8],   // b_hh2 [204]
        (const float*)d_in[9],   // W_lin [1,51]
        (const float*)d_in[10],  // b_lin [1]
        (float*)d_out);          // out [B, 1100]
}